// round 2
// baseline (speedup 1.0000x reference)
#include <cuda_runtime.h>
#include <cstddef>

#define DB 4
#define DE 16
#define DN 1024
#define DD 512
#define NBE (DB * DE)

// Scratch (allocation-free rule: __device__ globals)
__device__ __align__(256) float g_q[(size_t)NBE * DN * DD];
__device__ __align__(256) float g_k[(size_t)NBE * DN * DD];
__device__ __align__(256) float g_v[(size_t)NBE * DN * DD];
__device__ __align__(256) float g_att[(size_t)NBE * DD * DD];

// ---- packed f32x2 helpers (FFMA2 path, PTX-only per SASS_QUICKREF) ----
__device__ __forceinline__ unsigned long long pk2(float x, float y) {
    unsigned long long r;
    asm("mov.b64 %0, {%1, %2};" : "=l"(r) : "f"(x), "f"(y));
    return r;
}
__device__ __forceinline__ void fma2(unsigned long long& d, unsigned long long a, unsigned long long b) {
    asm("fma.rn.f32x2 %0, %1, %2, %0;" : "+l"(d) : "l"(a), "l"(b));
}
__device__ __forceinline__ float2 upk(unsigned long long v) {
    float2 r;
    asm("mov.b64 {%0, %1}, %2;" : "=f"(r.x), "=f"(r.y) : "l"(v));
    return r;
}

// ---------------------------------------------------------------------------
// Batched tiled GEMM, fp32, 128x128 tile, BK=16, 256 threads, 8x8/thread
// TRANSA=false: C[m,n] = sum_k A[m,k]*B[k,n]   (A row-major M x K)
// TRANSA=true : C[m,n] = sum_k A[k,m]*B[k,n]   (A row-major K x M, i.e. A^T B)
// Batch: A += be*sA ; B += (be%modB)*sB ; C += be*sC
// ---------------------------------------------------------------------------
template <bool TRANSA>
__global__ __launch_bounds__(256) void gemm_kernel(
    const float* __restrict__ Ab, const float* __restrict__ Bb, float* __restrict__ Cb,
    int M, int Nd, int Kd, int lda, int ldb, int ldc,
    long sA, long sB, long sC, int modB)
{
    const int be = blockIdx.y;
    const float* A = Ab + (size_t)be * sA;
    const float* Bp = Bb + (size_t)(be % modB) * sB;
    float* C = Cb + (size_t)be * sC;

    const int ntile = Nd >> 7;
    const int m0 = (blockIdx.x / ntile) << 7;
    const int n0 = (blockIdx.x % ntile) << 7;

    __shared__ float As[16][128];
    __shared__ float Bs[16][128];

    const int t = threadIdx.x;
    const int tx = t & 15, ty = t >> 4;

    // B loader: 16 rows x 128 cols, 8 floats/thread
    const int brow = t >> 4;
    const int bcol = (t & 15) * 8;
    const float* Bptr = Bp + (size_t)brow * ldb + n0 + bcol;

    // A loader
    int arow, acol;
    const float* Aptr;
    if (TRANSA) {
        arow = t >> 4; acol = (t & 15) * 8;
        Aptr = A + (size_t)arow * lda + m0 + acol;
    } else {
        arow = t >> 1; acol = (t & 1) * 8;
        Aptr = A + (size_t)(m0 + arow) * lda + acol;
    }

    unsigned long long acc[8][4];
#pragma unroll
    for (int i = 0; i < 8; i++)
#pragma unroll
        for (int j = 0; j < 4; j++) acc[i][j] = 0ull;

    for (int kt = 0; kt < Kd; kt += 16) {
        float4 a0 = *(const float4*)(Aptr);
        float4 a1 = *(const float4*)(Aptr + 4);
        float4 b0 = *(const float4*)(Bptr);
        float4 b1 = *(const float4*)(Bptr + 4);

        if (TRANSA) {
            *(float4*)&As[arow][acol]     = a0;
            *(float4*)&As[arow][acol + 4] = a1;
            Aptr += (size_t)16 * lda;
        } else {
            As[acol + 0][arow] = a0.x; As[acol + 1][arow] = a0.y;
            As[acol + 2][arow] = a0.z; As[acol + 3][arow] = a0.w;
            As[acol + 4][arow] = a1.x; As[acol + 5][arow] = a1.y;
            As[acol + 6][arow] = a1.z; As[acol + 7][arow] = a1.w;
            Aptr += 16;
        }
        *(float4*)&Bs[brow][bcol]     = b0;
        *(float4*)&Bs[brow][bcol + 4] = b1;
        Bptr += (size_t)16 * ldb;
        __syncthreads();

#pragma unroll
        for (int kk = 0; kk < 16; kk++) {
            float4 av0 = *(const float4*)&As[kk][ty * 4];
            float4 av1 = *(const float4*)&As[kk][ty * 4 + 64];
            unsigned long long pa[8];
            pa[0] = pk2(av0.x, av0.x); pa[1] = pk2(av0.y, av0.y);
            pa[2] = pk2(av0.z, av0.z); pa[3] = pk2(av0.w, av0.w);
            pa[4] = pk2(av1.x, av1.x); pa[5] = pk2(av1.y, av1.y);
            pa[6] = pk2(av1.z, av1.z); pa[7] = pk2(av1.w, av1.w);
            ulonglong2 bq0 = *(const ulonglong2*)&Bs[kk][tx * 4];
            ulonglong2 bq1 = *(const ulonglong2*)&Bs[kk][tx * 4 + 64];
#pragma unroll
            for (int i = 0; i < 8; i++) {
                fma2(acc[i][0], pa[i], bq0.x);
                fma2(acc[i][1], pa[i], bq0.y);
                fma2(acc[i][2], pa[i], bq1.x);
                fma2(acc[i][3], pa[i], bq1.y);
            }
        }
        __syncthreads();
    }

    // epilogue: rows {i4*64 + ty*4 + ii}, cols {j4*64 + tx*4 .. +3}
#pragma unroll
    for (int i4 = 0; i4 < 2; i4++) {
#pragma unroll
        for (int ii = 0; ii < 4; ii++) {
            const int m = m0 + i4 * 64 + ty * 4 + ii;
            float* Crow = C + (size_t)m * ldc;
#pragma unroll
            for (int j4 = 0; j4 < 2; j4++) {
                float2 p0 = upk(acc[i4 * 4 + ii][j4 * 2]);
                float2 p1 = upk(acc[i4 * 4 + ii][j4 * 2 + 1]);
                float4 o = make_float4(p0.x, p0.y, p1.x, p1.y);
                *(float4*)&Crow[n0 + j4 * 64 + tx * 4] = o;
            }
        }
    }
}

// ---------------------------------------------------------------------------
// Row softmax over last dim (512), one block (128 thr) per row, 4 elems/thread
// ---------------------------------------------------------------------------
__global__ void softmax_rows(float* __restrict__ att)
{
    __shared__ float smax[4];
    __shared__ float ssum[4];
    const int row = blockIdx.x;
    float4* p = (float4*)(att + (size_t)row * DD);
    const int t = threadIdx.x;

    float4 v = p[t];
    float m = fmaxf(fmaxf(v.x, v.y), fmaxf(v.z, v.w));
#pragma unroll
    for (int o = 16; o > 0; o >>= 1) m = fmaxf(m, __shfl_xor_sync(0xffffffffu, m, o));
    if ((t & 31) == 0) smax[t >> 5] = m;
    __syncthreads();
    m = fmaxf(fmaxf(smax[0], smax[1]), fmaxf(smax[2], smax[3]));

    v.x = expf(v.x - m); v.y = expf(v.y - m);
    v.z = expf(v.z - m); v.w = expf(v.w - m);
    float s = v.x + v.y + v.z + v.w;
#pragma unroll
    for (int o = 16; o > 0; o >>= 1) s += __shfl_xor_sync(0xffffffffu, s, o);
    if ((t & 31) == 0) ssum[t >> 5] = s;
    __syncthreads();
    s = ssum[0] + ssum[1] + ssum[2] + ssum[3];

    const float inv = 1.0f / s;
    v.x *= inv; v.y *= inv; v.z *= inv; v.w *= inv;
    p[t] = v;
}

extern "C" void kernel_launch(void* const* d_in, const int* in_sizes, int n_in,
                              void* d_out, int out_size)
{
    (void)in_sizes; (void)n_in; (void)out_size;
    const float* x  = (const float*)d_in[0];
    const float* w1 = (const float*)d_in[1];
    const float* w2 = (const float*)d_in[2];
    const float* w3 = (const float*)d_in[3];
    float* out = (float*)d_out;

    float *q, *k, *v, *att;
    cudaGetSymbolAddress((void**)&q,   g_q);
    cudaGetSymbolAddress((void**)&k,   g_k);
    cudaGetSymbolAddress((void**)&v,   g_v);
    cudaGetSymbolAddress((void**)&att, g_att);

    const long strND = (long)DN * DD;   // per-batch stride for N x D tensors
    const long strDD = (long)DD * DD;   // per-batch stride for D x D tensors

    dim3 blk(256);
    dim3 gProj(32, NBE);   // (1024/128)*(512/128) = 32 tiles
    dim3 gAtt(16, NBE);    // (512/128)*(512/128)  = 16 tiles

    // q/k/v = x @ w{1,2,3}   (M=1024, N=512, K=512), weights shared across b (modB=E)
    gemm_kernel<false><<<gProj, blk>>>(x, w1, q, DN, DD, DD, DD, DD, DD, strND, strDD, strND, DE);
    gemm_kernel<false><<<gProj, blk>>>(x, w2, k, DN, DD, DD, DD, DD, DD, strND, strDD, strND, DE);
    gemm_kernel<false><<<gProj, blk>>>(x, w3, v, DN, DD, DD, DD, DD, DD, strND, strDD, strND, DE);

    // att = q^T @ k          (M=512, N=512, K=1024)
    gemm_kernel<true><<<gAtt, blk>>>(q, k, att, DD, DD, DN, DD, DD, DD, strND, strND, strDD, NBE);

    // softmax over last dim
    softmax_rows<<<NBE * DD, 128>>>(att);

    // out = v @ att          (M=1024, N=512, K=512)
    gemm_kernel<false><<<gProj, blk>>>(v, att, out, DN, DD, DD, DD, DD, DD, strND, strDD, strND, NBE);
}

// round 6
// speedup vs baseline: 1.7054x; 1.7054x over previous
#include <cuda_runtime.h>
#include <cuda_bf16.h>
#include <cstdint>
#include <cstddef>

#define DB 4
#define DE 16
#define DN 1024
#define DD 512
#define NBE (DB * DE)

// Scratch (allocation-free rule: __device__ globals)
__device__ __align__(256) float g_q[(size_t)NBE * DN * DD];
__device__ __align__(256) float g_k[(size_t)NBE * DN * DD];
__device__ __align__(256) float g_v[(size_t)NBE * DN * DD];
__device__ __align__(256) float g_att[(size_t)NBE * DD * DD];

// ---------------- helpers ----------------
__device__ __forceinline__ uint32_t smem_u32(const void* p) {
    uint32_t a;
    asm("{ .reg .u64 t; cvta.to.shared.u64 t, %1; cvt.u32.u64 %0, t; }" : "=r"(a) : "l"(p));
    return a;
}
__device__ __forceinline__ void ldsm4(uint32_t* r, uint32_t addr) {
    asm volatile("ldmatrix.sync.aligned.m8n8.x4.shared.b16 {%0,%1,%2,%3}, [%4];"
                 : "=r"(r[0]), "=r"(r[1]), "=r"(r[2]), "=r"(r[3]) : "r"(addr));
}
__device__ __forceinline__ void ldsm4t(uint32_t* r, uint32_t addr) {
    asm volatile("ldmatrix.sync.aligned.m8n8.x4.trans.shared.b16 {%0,%1,%2,%3}, [%4];"
                 : "=r"(r[0]), "=r"(r[1]), "=r"(r[2]), "=r"(r[3]) : "r"(addr));
}
__device__ __forceinline__ void mma16816(float* d, const uint32_t* a, const uint32_t* b) {
    asm volatile(
        "mma.sync.aligned.m16n8k16.row.col.f32.bf16.bf16.f32 "
        "{%0,%1,%2,%3}, {%4,%5,%6,%7}, {%8,%9}, {%0,%1,%2,%3};"
        : "+f"(d[0]), "+f"(d[1]), "+f"(d[2]), "+f"(d[3])
        : "r"(a[0]), "r"(a[1]), "r"(a[2]), "r"(a[3]), "r"(b[0]), "r"(b[1]));
}
// split (x,y) fp32 -> hi bf16x2 + lo bf16x2
__device__ __forceinline__ void split2(float x, float y, uint32_t& h, uint32_t& l) {
    __nv_bfloat162 hb = __floats2bfloat162_rn(x, y);
    float2 hf = __bfloat1622float2(hb);
    __nv_bfloat162 lb = __floats2bfloat162_rn(x - hf.x, y - hf.y);
    h = reinterpret_cast<uint32_t&>(hb);
    l = reinterpret_cast<uint32_t&>(lb);
}

// SMEM layout per stage (bytes):
//   Ahi [128][40 bf16] stride 80B : 10240
//   Alo                           : 10240
//   Bhi [32][128 bf16] xor-swz    :  8192
//   Blo                           :  8192
static constexpr int AHI = 0;
static constexpr int ALO = 10240;
static constexpr int BHI = 20480;
static constexpr int BLO = 28672;
static constexpr int STG = 36864;
static constexpr int SMEM_REQ = 2 * STG;

// ---------------------------------------------------------------------------
// HMMA bf16-split GEMM. 128x128 CTA tile, BK=32, 256 thr (8 warps of 64x32).
// TRANSA=false: C[m,n] = sum_k A[m,k] B[k,n]   (A row-major M x K)
// TRANSA=true : C[m,n] = sum_k A[k,m] B[k,n]   (A row-major K x M)
// B row-major K x N. Batch: A += be*sA ; B += (be%modB)*sB ; C += be*sC
// ---------------------------------------------------------------------------
template <bool TRANSA>
__global__ __launch_bounds__(256, 1) void hmma_gemm(
    const float* __restrict__ Ab, const float* __restrict__ Bb, float* __restrict__ Cb,
    int lda, int ldb, int ldc, long sA, long sB, long sC, int modB, int ktiles, int ntile)
{
    extern __shared__ __align__(1024) char smem[];
    const uint32_t sbase = smem_u32(smem);

    const int t    = threadIdx.x;
    const int lane = t & 31;
    const int wid  = t >> 5;
    const int be   = blockIdx.y;
    const float* A = Ab + (size_t)be * sA;
    const float* B = Bb + (size_t)(be % modB) * sB;
    float*       C = Cb + (size_t)be * sC;

    const int m0 = (blockIdx.x / ntile) << 7;
    const int n0 = (blockIdx.x % ntile) << 7;

    // ---- loader index maps ----
    const int bk = t >> 3;             // B: k row 0..31
    const int bn = (t & 7) << 4;       // B: n start (16 floats)
    const float* Bptr = B + (size_t)bk * ldb + n0 + bn;

    const int am  = t >> 1;            // A no-trans: m row
    const int akc = (t & 1) << 4;      // A no-trans: k start (16 floats)
    const int akp = t & 15;            // A trans: k-pair -> rows 2akp, 2akp+1
    const int amc = (t >> 4) << 3;     // A trans: m start (8 floats)
    const float* Aptr = TRANSA
        ? A + (size_t)(2 * akp) * lda + m0 + amc
        : A + (size_t)(m0 + am) * lda + akc;

    // ---- compute index maps (per warp: 64x32 tile) ----
    const int mw = (wid >> 2) << 6;    // 0 or 64
    const int nw = (wid & 3) << 5;     // 0,32,64,96
    // A ldmatrix lane offset: row = mw + (lane&15), kbyte = (lane>>4)*16
    const uint32_t a_off = (uint32_t)(mw + (lane & 15)) * 80u + ((lane >> 4) << 4);
    // B ldmatrix.trans lane offsets: krow = lane&15 ; ncol per njp
    const int bkl = lane & 15;
    const int bnl = (lane >> 4) << 3;
    uint32_t b_off[2];
#pragma unroll
    for (int njp = 0; njp < 2; njp++)
        b_off[njp] = (uint32_t)bkl * 256u +
                     ((uint32_t)((nw + njp * 16 + bnl) << 1) ^ (uint32_t)((bkl & 7) << 4));

    float acc[4][4][4];
#pragma unroll
    for (int i = 0; i < 4; i++)
#pragma unroll
        for (int j = 0; j < 4; j++)
#pragma unroll
            for (int r = 0; r < 4; r++) acc[i][j][r] = 0.0f;

    float4 pa[4], pb[4];

    // ---- prologue: load tile 0, store stage 0 ----
#pragma unroll
    for (int q = 0; q < 4; q++) pb[q] = *(const float4*)(Bptr + q * 4);
    if (TRANSA) {
        pa[0] = *(const float4*)(Aptr);       pa[1] = *(const float4*)(Aptr + 4);
        pa[2] = *(const float4*)(Aptr + lda); pa[3] = *(const float4*)(Aptr + lda + 4);
    } else {
#pragma unroll
        for (int q = 0; q < 4; q++) pa[q] = *(const float4*)(Aptr + q * 4);
    }

    for (int kt = 0; kt < ktiles; kt++) {
        // ---- store prefetched regs -> stage kt&1 ----
        {
            char* sb = smem + (kt & 1) * STG;
            // B tiles
#pragma unroll
            for (int j = 0; j < 2; j++) {
                uint4 H, L;
                split2(pb[2 * j].x, pb[2 * j].y, H.x, L.x);
                split2(pb[2 * j].z, pb[2 * j].w, H.y, L.y);
                split2(pb[2 * j + 1].x, pb[2 * j + 1].y, H.z, L.z);
                split2(pb[2 * j + 1].z, pb[2 * j + 1].w, H.w, L.w);
                uint32_t off = (uint32_t)bk * 256u +
                               (((uint32_t)(bn << 1) + (uint32_t)(j << 4)) ^ (uint32_t)((bk & 7) << 4));
                *(uint4*)(sb + BHI + off) = H;
                *(uint4*)(sb + BLO + off) = L;
            }
            // A tiles
            if (TRANSA) {
                float v0[8] = {pa[0].x, pa[0].y, pa[0].z, pa[0].w, pa[1].x, pa[1].y, pa[1].z, pa[1].w};
                float v1[8] = {pa[2].x, pa[2].y, pa[2].z, pa[2].w, pa[3].x, pa[3].y, pa[3].z, pa[3].w};
#pragma unroll
                for (int i = 0; i < 8; i++) {
                    uint32_t h, l;
                    split2(v0[i], v1[i], h, l);   // (k, k+1) pair at m = amc+i
                    uint32_t off = (uint32_t)(amc + i) * 80u + (uint32_t)(akp << 2);
                    *(uint32_t*)(sb + AHI + off) = h;
                    *(uint32_t*)(sb + ALO + off) = l;
                }
            } else {
#pragma unroll
                for (int j = 0; j < 2; j++) {
                    uint4 H, L;
                    split2(pa[2 * j].x, pa[2 * j].y, H.x, L.x);
                    split2(pa[2 * j].z, pa[2 * j].w, H.y, L.y);
                    split2(pa[2 * j + 1].x, pa[2 * j + 1].y, H.z, L.z);
                    split2(pa[2 * j + 1].z, pa[2 * j + 1].w, H.w, L.w);
                    uint32_t off = (uint32_t)am * 80u + (uint32_t)(akc << 1) + (uint32_t)(j << 4);
                    *(uint4*)(sb + AHI + off) = H;
                    *(uint4*)(sb + ALO + off) = L;
                }
            }
        }
        __syncthreads();

        // ---- prefetch next tile ----
        if (kt + 1 < ktiles) {
            const float* Bp = Bptr + (size_t)(kt + 1) * 32 * ldb;
#pragma unroll
            for (int q = 0; q < 4; q++) pb[q] = *(const float4*)(Bp + q * 4);
            if (TRANSA) {
                const float* Ap = Aptr + (size_t)(kt + 1) * 32 * lda;
                pa[0] = *(const float4*)(Ap);       pa[1] = *(const float4*)(Ap + 4);
                pa[2] = *(const float4*)(Ap + lda); pa[3] = *(const float4*)(Ap + lda + 4);
            } else {
                const float* Ap = Aptr + (size_t)(kt + 1) * 32;
#pragma unroll
                for (int q = 0; q < 4; q++) pa[q] = *(const float4*)(Ap + q * 4);
            }
        }

        // ---- compute on stage kt&1 ----
        {
            const uint32_t sb32 = sbase + (uint32_t)((kt & 1) * STG);
            const uint32_t ah = sb32 + AHI, al = sb32 + ALO;
            const uint32_t bh = sb32 + BHI, bl = sb32 + BLO;
#pragma unroll
            for (int ks = 0; ks < 2; ks++) {
                uint32_t Ah[4][4], Al[4][4], Bh[2][4], Bl[2][4];
#pragma unroll
                for (int mi = 0; mi < 4; mi++) {
                    const uint32_t ao = a_off + (uint32_t)(mi * 16 * 80) + (uint32_t)(ks * 32);
                    ldsm4(Ah[mi], ah + ao);
                    ldsm4(Al[mi], al + ao);
                }
#pragma unroll
                for (int njp = 0; njp < 2; njp++) {
                    const uint32_t bo = b_off[njp] + (uint32_t)(ks * 16 * 256);
                    ldsm4t(Bh[njp], bh + bo);
                    ldsm4t(Bl[njp], bl + bo);
                }
#pragma unroll
                for (int mi = 0; mi < 4; mi++)
#pragma unroll
                    for (int njp = 0; njp < 2; njp++)
#pragma unroll
                        for (int j = 0; j < 2; j++) {
                            float* d = acc[mi][njp * 2 + j];
                            mma16816(d, Ah[mi], &Bh[njp][2 * j]);  // hi*hi
                            mma16816(d, Ah[mi], &Bl[njp][2 * j]);  // hi*lo
                            mma16816(d, Al[mi], &Bh[njp][2 * j]);  // lo*hi
                        }
            }
        }
        __syncthreads();
    }

    // ---- epilogue: accumulators -> C (fp32) ----
    const int cm = m0 + mw + (lane >> 2);
    const int cn = n0 + nw + ((lane & 3) << 1);
#pragma unroll
    for (int mi = 0; mi < 4; mi++) {
#pragma unroll
        for (int nj = 0; nj < 4; nj++) {
            float* d = acc[mi][nj];
            float* c0 = C + (size_t)(cm + mi * 16) * ldc + cn + nj * 8;
            float* c1 = c0 + (size_t)8 * ldc;
            c0[0] = d[0]; c0[1] = d[1];
            c1[0] = d[2]; c1[1] = d[3];
        }
    }
}

// ---------------------------------------------------------------------------
// Row softmax over last dim (512), one block (128 thr) per row
// ---------------------------------------------------------------------------
__global__ void softmax_rows(float* __restrict__ att)
{
    __shared__ float smax[4];
    __shared__ float ssum[4];
    const int row = blockIdx.x;
    float4* p = (float4*)(att + (size_t)row * DD);
    const int t = threadIdx.x;

    float4 v = p[t];
    float m = fmaxf(fmaxf(v.x, v.y), fmaxf(v.z, v.w));
#pragma unroll
    for (int o = 16; o > 0; o >>= 1) m = fmaxf(m, __shfl_xor_sync(0xffffffffu, m, o));
    if ((t & 31) == 0) smax[t >> 5] = m;
    __syncthreads();
    m = fmaxf(fmaxf(smax[0], smax[1]), fmaxf(smax[2], smax[3]));

    v.x = expf(v.x - m); v.y = expf(v.y - m);
    v.z = expf(v.z - m); v.w = expf(v.w - m);
    float s = v.x + v.y + v.z + v.w;
#pragma unroll
    for (int o = 16; o > 0; o >>= 1) s += __shfl_xor_sync(0xffffffffu, s, o);
    if ((t & 31) == 0) ssum[t >> 5] = s;
    __syncthreads();
    s = ssum[0] + ssum[1] + ssum[2] + ssum[3];

    const float inv = 1.0f / s;
    v.x *= inv; v.y *= inv; v.z *= inv; v.w *= inv;
    p[t] = v;
}

extern "C" void kernel_launch(void* const* d_in, const int* in_sizes, int n_in,
                              void* d_out, int out_size)
{
    (void)in_sizes; (void)n_in; (void)out_size;
    const float* x  = (const float*)d_in[0];
    const float* w1 = (const float*)d_in[1];
    const float* w2 = (const float*)d_in[2];
    const float* w3 = (const float*)d_in[3];
    float* out = (float*)d_out;

    float *q, *k, *v, *att;
    cudaGetSymbolAddress((void**)&q,   g_q);
    cudaGetSymbolAddress((void**)&k,   g_k);
    cudaGetSymbolAddress((void**)&v,   g_v);
    cudaGetSymbolAddress((void**)&att, g_att);

    cudaFuncSetAttribute(hmma_gemm<false>, cudaFuncAttributeMaxDynamicSharedMemorySize, SMEM_REQ);
    cudaFuncSetAttribute(hmma_gemm<true>,  cudaFuncAttributeMaxDynamicSharedMemorySize, SMEM_REQ);

    const long strND = (long)DN * DD;
    const long strDD = (long)DD * DD;

    dim3 blk(256);
    dim3 gProj(32, NBE);   // (1024/128)*(512/128)
    dim3 gAtt(16, NBE);    // (512/128)*(512/128)

    // q/k/v = x @ w{1,2,3}   (M=1024, N=512, K=512)
    hmma_gemm<false><<<gProj, blk, SMEM_REQ>>>(x, w1, q, DD, DD, DD, strND, strDD, strND, DE, 16, 4);
    hmma_gemm<false><<<gProj, blk, SMEM_REQ>>>(x, w2, k, DD, DD, DD, strND, strDD, strND, DE, 16, 4);
    hmma_gemm<false><<<gProj, blk, SMEM_REQ>>>(x, w3, v, DD, DD, DD, strND, strDD, strND, DE, 16, 4);

    // att = q^T @ k          (M=512, N=512, K=1024)
    hmma_gemm<true><<<gAtt, blk, SMEM_REQ>>>(q, k, att, DD, DD, DD, strND, strND, strDD, NBE, 32, 4);

    // softmax over last dim
    softmax_rows<<<NBE * DD, 128>>>(att);

    // out = v @ att          (M=1024, N=512, K=512)
    hmma_gemm<false><<<gProj, blk, SMEM_REQ>>>(v, att, out, DD, DD, DD, strND, strDD, strND, NBE, 16, 4);
}